// round 16
// baseline (speedup 1.0000x reference)
#include <cuda_runtime.h>
#include <cuda_bf16.h>
#include <math.h>
#include <stdint.h>

#define Bsz 512
#define Tt  512
#define Ee  32
#define H1C 128
#define G1  512
#define H2C 64
#define G2  256
#define VV  32000
#define RWS 4
#define NR  (Bsz * Tt)

typedef unsigned long long ull;

static __device__ float g_zx1[(size_t)NR * G1];
static __device__ float g_zx2[(size_t)NR * G2];
static __device__ float g_h1[(size_t)NR * H1C];
static __device__ float g_h2[Bsz * H2C];

// ---------------------------------------------------------------------------
// helpers
// ---------------------------------------------------------------------------
__device__ __forceinline__ float sigf(float x) {
    float ev = __expf(-x);
    return __fdividef(1.0f, 1.0f + ev);
}
__device__ __forceinline__ ull pack2(float a, float b) {
    ull r; asm("mov.b64 %0, {%1,%2};" : "=l"(r) : "f"(a), "f"(b)); return r;
}
__device__ __forceinline__ void ffma2(ull& d, ull a, ull b) {
    asm("fma.rn.f32x2 %0, %1, %2, %0;" : "+l"(d) : "l"(a), "l"(b));
}
__device__ __forceinline__ float2 unpk2(ull v) {
    float2 r; asm("mov.b64 {%0,%1}, %2;" : "=f"(r.x), "=f"(r.y) : "l"(v)); return r;
}
__device__ __forceinline__ void mma_bf16(float4& c, const uint32_t* a, const uint32_t* b) {
    asm volatile("mma.sync.aligned.m16n8k16.row.col.f32.bf16.bf16.f32 "
        "{%0,%1,%2,%3}, {%4,%5,%6,%7}, {%8,%9}, {%0,%1,%2,%3};"
        : "+f"(c.x), "+f"(c.y), "+f"(c.z), "+f"(c.w)
        : "r"(a[0]), "r"(a[1]), "r"(a[2]), "r"(a[3]), "r"(b[0]), "r"(b[1]));
}
__device__ __forceinline__ void split_bf16(float x, __nv_bfloat16& h, __nv_bfloat16& l) {
    h = __float2bfloat16(x);
    l = __float2bfloat16(x - __bfloat162float(h));
}

// ---------------------------------------------------------------------------
// zx1 = gather(emb, ids) @ W1 — bf16x3 mma (R8 exact). Idempotent: launched
// twice this round so (total - 3075us) measures its wall-clock duration.
// ---------------------------------------------------------------------------
#define PK1 34
#define ZX1_SMEM ((128*PK1*2 + 512*PK1*2) * 2)

__global__ void __launch_bounds__(256, 1) zx1_gemm(
    const int* __restrict__ ids, const float* __restrict__ emb,
    const float* __restrict__ w1)
{
    extern __shared__ __nv_bfloat16 smb[];
    __nv_bfloat16* aH = smb;
    __nv_bfloat16* aL = aH + 128*PK1;
    __nv_bfloat16* bH = aL + 128*PK1;
    __nv_bfloat16* bL = bH + 512*PK1;

    const int tid = threadIdx.x, wid = tid >> 5, lane = tid & 31;
    const size_t R0 = (size_t)blockIdx.x * 128;

    for (int idx = tid; idx < Ee * G1; idx += 256) {
        int k = idx >> 9, g = idx & 511;
        split_bf16(w1[idx], bH[g*PK1 + k], bL[g*PK1 + k]);
    }
    {
        int row = tid >> 1;
        int id = ids[R0 + row];
        int base = (tid & 1) * 16;
        const float* er = emb + (size_t)id * Ee + base;
        #pragma unroll
        for (int q = 0; q < 16; q++)
            split_bf16(er[q], aH[row*PK1 + base + q], aL[row*PK1 + base + q]);
    }
    __syncthreads();

    const int rbase = wid * 16;
    const int tr = lane >> 2;
    const int tk = (lane & 3) * 2;

    uint32_t ah[2][4], al[2][4];
    #pragma unroll
    for (int kt = 0; kt < 2; kt++) {
        int k0 = kt*16 + tk;
        ah[kt][0] = *(const uint32_t*)&aH[(rbase + tr    )*PK1 + k0];
        ah[kt][1] = *(const uint32_t*)&aH[(rbase + tr + 8)*PK1 + k0];
        ah[kt][2] = *(const uint32_t*)&aH[(rbase + tr    )*PK1 + k0 + 8];
        ah[kt][3] = *(const uint32_t*)&aH[(rbase + tr + 8)*PK1 + k0 + 8];
        al[kt][0] = *(const uint32_t*)&aL[(rbase + tr    )*PK1 + k0];
        al[kt][1] = *(const uint32_t*)&aL[(rbase + tr + 8)*PK1 + k0];
        al[kt][2] = *(const uint32_t*)&aL[(rbase + tr    )*PK1 + k0 + 8];
        al[kt][3] = *(const uint32_t*)&aL[(rbase + tr + 8)*PK1 + k0 + 8];
    }

    float* op = g_zx1 + R0 * G1;
    #pragma unroll 4
    for (int nt = 0; nt < 64; nt++) {
        int nb = nt * 8;
        uint32_t bh[2][2], bl[2][2];
        #pragma unroll
        for (int kt = 0; kt < 2; kt++) {
            int k0 = kt*16 + tk;
            bh[kt][0] = *(const uint32_t*)&bH[(nb + tr)*PK1 + k0];
            bh[kt][1] = *(const uint32_t*)&bH[(nb + tr)*PK1 + k0 + 8];
            bl[kt][0] = *(const uint32_t*)&bL[(nb + tr)*PK1 + k0];
            bl[kt][1] = *(const uint32_t*)&bL[(nb + tr)*PK1 + k0 + 8];
        }
        float4 acc = make_float4(0.f, 0.f, 0.f, 0.f);
        #pragma unroll
        for (int kt = 0; kt < 2; kt++) {
            mma_bf16(acc, ah[kt], bh[kt]);
            mma_bf16(acc, ah[kt], bl[kt]);
            mma_bf16(acc, al[kt], bh[kt]);
        }
        *(float2*)&op[(size_t)(rbase + tr    )*G1 + nb + tk] = make_float2(acc.x, acc.y);
        *(float2*)&op[(size_t)(rbase + tr + 8)*G1 + nb + tk] = make_float2(acc.z, acc.w);
    }
}

// ---------------------------------------------------------------------------
// zx2 = g_h1 @ W2 — bf16x3 mma (R8 exact). grid (2048, 2). Launch slot 4
// this round -> ncu capture target.
// ---------------------------------------------------------------------------
#define PK2 132
#define ZX2_SMEM ((128*PK2*2 + 128*PK2*2) * 2)

__global__ void __launch_bounds__(256, 1) zx2_gemm(const float* __restrict__ w2)
{
    extern __shared__ __nv_bfloat16 smb[];
    __nv_bfloat16* aH = smb;
    __nv_bfloat16* aL = aH + 128*PK2;
    __nv_bfloat16* bH = aL + 128*PK2;
    __nv_bfloat16* bL = bH + 128*PK2;

    const int tid = threadIdx.x, wid = tid >> 5, lane = tid & 31;
    const size_t R0 = (size_t)blockIdx.x * 128;
    const int gb = blockIdx.y * 128;

    for (int idx = tid; idx < 128 * H1C; idx += 256) {
        int k = idx >> 7, gl = idx & 127;
        split_bf16(w2[k*G2 + gb + gl], bH[gl*PK2 + k], bL[gl*PK2 + k]);
    }
    for (int idx = tid; idx < 128 * H1C; idx += 256)
        split_bf16(g_h1[R0*H1C + idx], aH[(idx >> 7)*PK2 + (idx & 127)],
                   aL[(idx >> 7)*PK2 + (idx & 127)]);
    __syncthreads();

    const int rbase = wid * 16;
    const int tr = lane >> 2;
    const int tk = (lane & 3) * 2;

    uint32_t ah[8][4], al[8][4];
    #pragma unroll
    for (int kt = 0; kt < 8; kt++) {
        int k0 = kt*16 + tk;
        ah[kt][0] = *(const uint32_t*)&aH[(rbase + tr    )*PK2 + k0];
        ah[kt][1] = *(const uint32_t*)&aH[(rbase + tr + 8)*PK2 + k0];
        ah[kt][2] = *(const uint32_t*)&aH[(rbase + tr    )*PK2 + k0 + 8];
        ah[kt][3] = *(const uint32_t*)&aH[(rbase + tr + 8)*PK2 + k0 + 8];
        al[kt][0] = *(const uint32_t*)&aL[(rbase + tr    )*PK2 + k0];
        al[kt][1] = *(const uint32_t*)&aL[(rbase + tr + 8)*PK2 + k0];
        al[kt][2] = *(const uint32_t*)&aL[(rbase + tr    )*PK2 + k0 + 8];
        al[kt][3] = *(const uint32_t*)&aL[(rbase + tr + 8)*PK2 + k0 + 8];
    }

    float* op = g_zx2 + R0 * G2 + gb;
    #pragma unroll 2
    for (int nt = 0; nt < 16; nt++) {
        int nb = nt * 8;
        float4 acc = make_float4(0.f, 0.f, 0.f, 0.f);
        #pragma unroll
        for (int kt = 0; kt < 8; kt++) {
            int k0 = kt*16 + tk;
            uint32_t bh[2], bl[2];
            bh[0] = *(const uint32_t*)&bH[(nb + tr)*PK2 + k0];
            bh[1] = *(const uint32_t*)&bH[(nb + tr)*PK2 + k0 + 8];
            bl[0] = *(const uint32_t*)&bL[(nb + tr)*PK2 + k0];
            bl[1] = *(const uint32_t*)&bL[(nb + tr)*PK2 + k0 + 8];
            mma_bf16(acc, ah[kt], bh);
            mma_bf16(acc, ah[kt], bl);
            mma_bf16(acc, al[kt], bh);
        }
        *(float2*)&op[(size_t)(rbase + tr    )*G2 + nb + tk] = make_float2(acc.x, acc.y);
        *(float2*)&op[(size_t)(rbase + tr + 8)*G2 + nb + tk] = make_float2(acc.z, acc.w);
    }
}

// ---------------------------------------------------------------------------
// LSTM1 recurrence (k=128) + BN1 — R8 exact. 512 threads.
// ---------------------------------------------------------------------------
#define SMEM1_BYTES (48*G1*8 + 512*16 + 512*4)

__global__ void __launch_bounds__(512, 1) lstm1_kernel(
    const float* __restrict__ u1, const float* __restrict__ b1,
    const float* __restrict__ g1, const float* __restrict__ be1,
    const float* __restrict__ m1, const float* __restrict__ v1)
{
    extern __shared__ char smraw[];
    ull*    sUp = (ull*)smraw;               // [48][512] u1 rows 32..127 pairs
    float4* sZ4 = (float4*)(sUp + 48*G1);    // [512]
    float*  sV  = (float*)(sZ4 + 512);       // [64 pairs][4][2] = 512 floats

    const int j  = threadIdx.x;
    const int r0 = blockIdx.x * RWS;
    const float* zx = g_zx1;

    ull rU[16];
    #pragma unroll
    for (int i = 0; i < 16; i++)
        rU[i] = pack2(u1[(2*i)*G1 + j], u1[(2*i+1)*G1 + j]);
    for (int i = 0; i < 48; i++)
        sUp[i*G1 + j] = pack2(u1[(32+2*i)*G1 + j], u1[(33+2*i)*G1 + j]);
    const float b1j = b1[j];

    const int rr = j >> 7, m = j & 127;
    const float bnsc = g1[m] / sqrtf(v1[m] + 1e-3f);
    const float bnsh = be1[m] - bnsc * m1[m];
    float creg = 0.f;

    sV[j] = 0.f;
    __syncthreads();

    float pz[4];
    #pragma unroll
    for (int i = 0; i < 4; i++)
        pz[i] = zx[((size_t)(r0 + i)*Tt + 0)*G1 + j];

    for (int t = 0; t < Tt; t++) {
        float nz[4] = {0.f, 0.f, 0.f, 0.f};
        const bool pf = (t + 1 < Tt);
        if (pf) {
            #pragma unroll
            for (int i = 0; i < 4; i++)
                nz[i] = zx[((size_t)(r0 + i)*Tt + t + 1)*G1 + j];
        }
        ull a0 = pack2(pz[0], b1j);
        ull a1 = pack2(pz[1], b1j);
        ull a2 = pack2(pz[2], b1j);
        ull a3 = pack2(pz[3], b1j);

        const ulonglong2* hv2 = (const ulonglong2*)sV;
        #pragma unroll
        for (int i = 0; i < 16; i++) {
            ulonglong2 hA = hv2[i*2];
            ulonglong2 hB = hv2[i*2 + 1];
            ffma2(a0, rU[i], hA.x);
            ffma2(a1, rU[i], hA.y);
            ffma2(a2, rU[i], hB.x);
            ffma2(a3, rU[i], hB.y);
        }
        #pragma unroll 8
        for (int i = 0; i < 48; i++) {
            ull u2 = sUp[i*G1 + j];
            ulonglong2 hA = hv2[(16+i)*2];
            ulonglong2 hB = hv2[(16+i)*2 + 1];
            ffma2(a0, u2, hA.x);
            ffma2(a1, u2, hA.y);
            ffma2(a2, u2, hB.x);
            ffma2(a3, u2, hB.y);
        }
        float2 f0 = unpk2(a0), f1 = unpk2(a1), f2 = unpk2(a2), f3 = unpk2(a3);
        sZ4[j] = make_float4(f0.x + f0.y, f1.x + f1.y, f2.x + f2.y, f3.x + f3.y);
        __syncthreads();

        const float* zf = (const float*)sZ4;
        float zi = zf[(m      )*4 + rr];
        float zfv= zf[(m + 128)*4 + rr];
        float zg = zf[(m + 256)*4 + rr];
        float zo = zf[(m + 384)*4 + rr];
        float ig = sigf(zi), fg = sigf(zfv), og = sigf(zo);
        float gg = fmaxf(zg, 0.f);
        creg = fmaf(fg, creg, ig * gg);
        float h = og * fmaxf(creg, 0.f);
        sV[(m>>1)*8 + rr*2 + (m&1)] = h;
        g_h1[((size_t)(r0 + rr)*Tt + t)*H1C + m] = fmaf(h, bnsc, bnsh);
        #pragma unroll
        for (int i = 0; i < 4; i++) pz[i] = nz[i];
        __syncthreads();
    }
}

// ---------------------------------------------------------------------------
// LSTM2 recurrence (k=64) + BN2 — R8 exact. 512 threads, k halves, reg weights.
// ---------------------------------------------------------------------------
#define SMEM2_BYTES (512*16 + 256*4)

__global__ void __launch_bounds__(512, 1) lstm2_kernel(
    const float* __restrict__ u2, const float* __restrict__ b2,
    const float* __restrict__ g2, const float* __restrict__ be2,
    const float* __restrict__ m2, const float* __restrict__ v2)
{
    extern __shared__ char smraw[];
    float4* sZp = (float4*)smraw;            // [2][256]
    float*  sV  = (float*)(sZp + 512);       // [32 pairs][4][2]

    const int j    = threadIdx.x;
    const int jc   = j & 255;
    const int half = j >> 8;
    const int r0   = blockIdx.x * RWS;
    const float* zx = g_zx2;

    ull rW[16];
    #pragma unroll
    for (int p = 0; p < 16; p++)
        rW[p] = pack2(u2[(32*half + 2*p)*G2 + jc], u2[(32*half + 2*p + 1)*G2 + jc]);
    const float bj = b2[jc];

    const int rr = jc >> 6, m = j & 63;
    const float bnsc = g2[m] / sqrtf(v2[m] + 1e-3f);
    const float bnsh = be2[m] - bnsc * m2[m];
    float creg = 0.f;

    if (j < 256) sV[j] = 0.f;
    __syncthreads();

    float pz[4] = {0.f, 0.f, 0.f, 0.f};
    if (half == 0) {
        #pragma unroll
        for (int i = 0; i < 4; i++)
            pz[i] = zx[((size_t)(r0 + i)*Tt + 0)*G2 + jc];
    }

    for (int t = 0; t < Tt; t++) {
        float nz[4] = {0.f, 0.f, 0.f, 0.f};
        const bool pf = (t + 1 < Tt);
        if (pf && half == 0) {
            #pragma unroll
            for (int i = 0; i < 4; i++)
                nz[i] = zx[((size_t)(r0 + i)*Tt + t + 1)*G2 + jc];
        }
        ull a0, a1, a2, a3;
        if (half == 0) {
            a0 = pack2(pz[0], bj); a1 = pack2(pz[1], bj);
            a2 = pack2(pz[2], bj); a3 = pack2(pz[3], bj);
        } else {
            a0 = pack2(0.f, 0.f); a1 = a0; a2 = a0; a3 = a0;
        }
        const ulonglong2* hv2 = (const ulonglong2*)sV;
        const int gb = 16 * half;
        #pragma unroll
        for (int p = 0; p < 16; p++) {
            ulonglong2 hA = hv2[(gb + p)*2];
            ulonglong2 hB = hv2[(gb + p)*2 + 1];
            ffma2(a0, rW[p], hA.x);
            ffma2(a1, rW[p], hA.y);
            ffma2(a2, rW[p], hB.x);
            ffma2(a3, rW[p], hB.y);
        }
        float2 f0 = unpk2(a0), f1 = unpk2(a1), f2 = unpk2(a2), f3 = unpk2(a3);
        sZp[half*G2 + jc] = make_float4(f0.x + f0.y, f1.x + f1.y, f2.x + f2.y, f3.x + f3.y);
        __syncthreads();

        if (j < 256) {
            const float* zf = (const float*)sZp;
            float zi = zf[(m      )*4 + rr] + zf[(256 + m      )*4 + rr];
            float zfv= zf[(m +  64)*4 + rr] + zf[(256 + m +  64)*4 + rr];
            float zg = zf[(m + 128)*4 + rr] + zf[(256 + m + 128)*4 + rr];
            float zo = zf[(m + 192)*4 + rr] + zf[(256 + m + 192)*4 + rr];
            float ig = sigf(zi), fg = sigf(zfv), og = sigf(zo);
            float gg = fmaxf(zg, 0.f);
            creg = fmaf(fg, creg, ig * gg);
            float h = og * fmaxf(creg, 0.f);
            sV[(m>>1)*8 + rr*2 + (m&1)] = h;
            if (t == Tt - 1)
                g_h2[(r0 + rr)*H2C + m] = fmaf(h, bnsc, bnsh);
        }
        #pragma unroll
        for (int i = 0; i < 4; i++) pz[i] = nz[i];
        __syncthreads();
    }
}

// ---------------------------------------------------------------------------
// head: logits + exp. 125 CTAs x 256 vocab columns.
// ---------------------------------------------------------------------------
#define H2T_STRIDE 514
#define SMEM3_BYTES (H2C * H2T_STRIDE * 4)

__global__ void __launch_bounds__(256, 1) head_kernel(
    const float* __restrict__ wd, const float* __restrict__ bd,
    float* __restrict__ out)
{
    extern __shared__ float sH2t[];
    const int j = threadIdx.x;
    const int v = blockIdx.x * 256 + j;

    for (int i = j; i < Bsz*H2C; i += 256) {
        int r = i >> 6, k = i & 63;
        sH2t[k*H2T_STRIDE + r] = g_h2[i];
    }
    ull rwd2[H2C];
    #pragma unroll
    for (int k = 0; k < H2C; k++) {
        float w = wd[(size_t)k*VV + v];
        rwd2[k] = pack2(w, w);
    }
    const float bdv = bd[v];
    const ull bb = pack2(bdv, bdv);
    __syncthreads();

    for (int r = 0; r < Bsz; r += 4) {
        ull a01 = bb, a23 = bb;
        #pragma unroll 16
        for (int k = 0; k < H2C; k++) {
            const float* hp = sH2t + k*H2T_STRIDE + r;
            ull h01 = *(const ull*)(hp);
            ull h23 = *(const ull*)(hp + 2);
            ffma2(a01, rwd2[k], h01);
            ffma2(a23, rwd2[k], h23);
        }
        float2 f01 = unpk2(a01), f23 = unpk2(a23);
        out[(size_t)(r + 0)*VV + v] = __expf(f01.x);
        out[(size_t)(r + 1)*VV + v] = __expf(f01.y);
        out[(size_t)(r + 2)*VV + v] = __expf(f23.x);
        out[(size_t)(r + 3)*VV + v] = __expf(f23.y);
    }
}

// ---------------------------------------------------------------------------
// per-row softmax normalize.
// ---------------------------------------------------------------------------
__global__ void __launch_bounds__(256, 1) softmax_norm_kernel(float* __restrict__ out)
{
    __shared__ float warp_s[8];
    __shared__ float inv_s;
    const int r = blockIdx.x;
    float4* p = (float4*)(out + (size_t)r * VV);

    float s = 0.f;
    for (int i = threadIdx.x; i < VV/4; i += 256) {
        float4 v = p[i];
        s += (v.x + v.y) + (v.z + v.w);
    }
    #pragma unroll
    for (int o = 16; o > 0; o >>= 1) s += __shfl_down_sync(0xffffffffu, s, o);
    if ((threadIdx.x & 31) == 0) warp_s[threadIdx.x >> 5] = s;
    __syncthreads();
    if (threadIdx.x == 0) {
        float tt = 0.f;
        #pragma unroll
        for (int i = 0; i < 8; i++) tt += warp_s[i];
        inv_s = 1.0f / tt;
    }
    __syncthreads();
    const float inv = inv_s;
    for (int i = threadIdx.x; i < VV/4; i += 256) {
        float4 v = p[i];
        v.x *= inv; v.y *= inv; v.z *= inv; v.w *= inv;
        p[i] = v;
    }
}

// ---------------------------------------------------------------------------
extern "C" void kernel_launch(void* const* d_in, const int* in_sizes, int n_in,
                              void* d_out, int out_size)
{
    const int*   ids = (const int*)  d_in[0];
    const float* emb = (const float*)d_in[1];
    const float* w1  = (const float*)d_in[2];
    const float* u1  = (const float*)d_in[3];
    const float* b1  = (const float*)d_in[4];
    const float* g1  = (const float*)d_in[5];
    const float* be1 = (const float*)d_in[6];
    const float* m1  = (const float*)d_in[7];
    const float* v1  = (const float*)d_in[8];
    const float* w2  = (const float*)d_in[9];
    const float* u2  = (const float*)d_in[10];
    const float* b2  = (const float*)d_in[11];
    const float* g2  = (const float*)d_in[12];
    const float* be2 = (const float*)d_in[13];
    const float* m2  = (const float*)d_in[14];
    const float* v2  = (const float*)d_in[15];
    const float* wd  = (const float*)d_in[16];
    const float* bd  = (const float*)d_in[17];
    float* out = (float*)d_out;

    cudaFuncSetAttribute(zx1_gemm,     cudaFuncAttributeMaxDynamicSharedMemorySize, ZX1_SMEM);
    cudaFuncSetAttribute(zx2_gemm,     cudaFuncAttributeMaxDynamicSharedMemorySize, ZX2_SMEM);
    cudaFuncSetAttribute(lstm1_kernel, cudaFuncAttributeMaxDynamicSharedMemorySize, SMEM1_BYTES);
    cudaFuncSetAttribute(lstm2_kernel, cudaFuncAttributeMaxDynamicSharedMemorySize, SMEM2_BYTES);
    cudaFuncSetAttribute(head_kernel,  cudaFuncAttributeMaxDynamicSharedMemorySize, SMEM3_BYTES);

    // MEASUREMENT ROUND: zx1 launched twice (idempotent) so
    // dur_total - 3075us = zx1 duration. This also places zx2 at launch
    // slot 4 = the ncu capture slot, giving its clean profile.
    zx1_gemm<<<NR/128, 256, ZX1_SMEM>>>(ids, emb, w1);   // 1
    zx1_gemm<<<NR/128, 256, ZX1_SMEM>>>(ids, emb, w1);   // 2 (duplicate)
    lstm1_kernel<<<Bsz/RWS, 512, SMEM1_BYTES>>>(u1, b1, g1, be1, m1, v1);  // 3
    zx2_gemm<<<dim3(NR/128, 2), 256, ZX2_SMEM>>>(w2);    // 4  <- captured
    lstm2_kernel<<<Bsz/RWS, 512, SMEM2_BYTES>>>(u2, b2, g2, be2, m2, v2);  // 5
    head_kernel<<<VV/256, 256, SMEM3_BYTES>>>(wd, bd, out);                // 6
    softmax_norm_kernel<<<Bsz, 256>>>(out);                                // 7
}

// round 17
// speedup vs baseline: 1.1857x; 1.1857x over previous
#include <cuda_runtime.h>
#include <cuda_bf16.h>
#include <math.h>
#include <stdint.h>

#define Bsz 512
#define Tt  512
#define Ee  32
#define H1C 128
#define G1  512
#define H2C 64
#define G2  256
#define VV  32000
#define RWS 4
#define NR  (Bsz * Tt)

typedef unsigned long long ull;

static __device__ float g_zx1[(size_t)NR * G1];
static __device__ float g_zx2[(size_t)NR * G2];
static __device__ __nv_bfloat16 g_h1h[(size_t)NR * H1C];  // h1 bf16 hi
static __device__ __nv_bfloat16 g_h1l[(size_t)NR * H1C];  // h1 bf16 lo
static __device__ __nv_bfloat16 g_w1h[Ee * G1], g_w1l[Ee * G1];     // [g][k] 512x32
static __device__ __nv_bfloat16 g_w2h[H1C * G2], g_w2l[H1C * G2];   // [g][k] 256x128
static __device__ float g_h2[Bsz * H2C];

// ---------------------------------------------------------------------------
// helpers
// ---------------------------------------------------------------------------
__device__ __forceinline__ float sigf(float x) {
    float ev = __expf(-x);
    return __fdividef(1.0f, 1.0f + ev);
}
__device__ __forceinline__ ull pack2(float a, float b) {
    ull r; asm("mov.b64 %0, {%1,%2};" : "=l"(r) : "f"(a), "f"(b)); return r;
}
__device__ __forceinline__ void ffma2(ull& d, ull a, ull b) {
    asm("fma.rn.f32x2 %0, %1, %2, %0;" : "+l"(d) : "l"(a), "l"(b));
}
__device__ __forceinline__ float2 unpk2(ull v) {
    float2 r; asm("mov.b64 {%0,%1}, %2;" : "=f"(r.x), "=f"(r.y) : "l"(v)); return r;
}
__device__ __forceinline__ void mma_bf16(float4& c, const uint32_t* a, const uint32_t* b) {
    asm volatile("mma.sync.aligned.m16n8k16.row.col.f32.bf16.bf16.f32 "
        "{%0,%1,%2,%3}, {%4,%5,%6,%7}, {%8,%9}, {%0,%1,%2,%3};"
        : "+f"(c.x), "+f"(c.y), "+f"(c.z), "+f"(c.w)
        : "r"(a[0]), "r"(a[1]), "r"(a[2]), "r"(a[3]), "r"(b[0]), "r"(b[1]));
}
__device__ __forceinline__ void split_bf16(float x, __nv_bfloat16& h, __nv_bfloat16& l) {
    h = __float2bfloat16(x);
    l = __float2bfloat16(x - __bfloat162float(h));
}

// ---------------------------------------------------------------------------
// prep: split W1, W2 into bf16 hi/lo, transposed to [g][k].
// ---------------------------------------------------------------------------
__global__ void __launch_bounds__(256, 1) split_w_kernel(
    const float* __restrict__ w1, const float* __restrict__ w2)
{
    int i = blockIdx.x * 256 + threadIdx.x;
    if (i < Ee * G1) {
        int k = i >> 9, g = i & 511;
        split_bf16(w1[i], g_w1h[g*Ee + k], g_w1l[g*Ee + k]);
    }
    int jx = i - Ee * G1;
    if (jx >= 0 && jx < H1C * G2) {
        int k = jx >> 8, g = jx & 255;
        split_bf16(w2[jx], g_w2h[g*H1C + k], g_w2l[g*H1C + k]);
    }
}

// ---------------------------------------------------------------------------
// zx1 = gather(emb, ids) @ W1 — bf16x3 mma. B prologue = pure copy.
// ---------------------------------------------------------------------------
#define PK1 34
#define ZX1_SMEM ((128*PK1*2 + 512*PK1*2) * 2)

__global__ void __launch_bounds__(256, 1) zx1_gemm(
    const int* __restrict__ ids, const float* __restrict__ emb)
{
    extern __shared__ __nv_bfloat16 smb[];
    __nv_bfloat16* aH = smb;
    __nv_bfloat16* aL = aH + 128*PK1;
    __nv_bfloat16* bH = aL + 128*PK1;
    __nv_bfloat16* bL = bH + 512*PK1;

    const int tid = threadIdx.x, wid = tid >> 5, lane = tid & 31;
    const size_t R0 = (size_t)blockIdx.x * 128;

    // B copy: g_w1h/[g][k] -> bH[g*34+k] via uint32 (2 bf16) chunks
    for (int c = tid; c < (Ee*G1)/2; c += 256) {
        int g = c >> 4, kc = (c & 15) * 2;
        *(uint32_t*)&bH[g*PK1 + kc] = ((const uint32_t*)g_w1h)[c];
        *(uint32_t*)&bL[g*PK1 + kc] = ((const uint32_t*)g_w1l)[c];
    }
    {
        int row = tid >> 1;
        int id = ids[R0 + row];
        int base = (tid & 1) * 16;
        const float* er = emb + (size_t)id * Ee + base;
        #pragma unroll
        for (int q = 0; q < 16; q++)
            split_bf16(er[q], aH[row*PK1 + base + q], aL[row*PK1 + base + q]);
    }
    __syncthreads();

    const int rbase = wid * 16;
    const int tr = lane >> 2;
    const int tk = (lane & 3) * 2;

    uint32_t ah[2][4], al[2][4];
    #pragma unroll
    for (int kt = 0; kt < 2; kt++) {
        int k0 = kt*16 + tk;
        ah[kt][0] = *(const uint32_t*)&aH[(rbase + tr    )*PK1 + k0];
        ah[kt][1] = *(const uint32_t*)&aH[(rbase + tr + 8)*PK1 + k0];
        ah[kt][2] = *(const uint32_t*)&aH[(rbase + tr    )*PK1 + k0 + 8];
        ah[kt][3] = *(const uint32_t*)&aH[(rbase + tr + 8)*PK1 + k0 + 8];
        al[kt][0] = *(const uint32_t*)&aL[(rbase + tr    )*PK1 + k0];
        al[kt][1] = *(const uint32_t*)&aL[(rbase + tr + 8)*PK1 + k0];
        al[kt][2] = *(const uint32_t*)&aL[(rbase + tr    )*PK1 + k0 + 8];
        al[kt][3] = *(const uint32_t*)&aL[(rbase + tr + 8)*PK1 + k0 + 8];
    }

    float* op = g_zx1 + R0 * G1;
    #pragma unroll 4
    for (int nt = 0; nt < 64; nt++) {
        int nb = nt * 8;
        uint32_t bh[2][2], bl[2][2];
        #pragma unroll
        for (int kt = 0; kt < 2; kt++) {
            int k0 = kt*16 + tk;
            bh[kt][0] = *(const uint32_t*)&bH[(nb + tr)*PK1 + k0];
            bh[kt][1] = *(const uint32_t*)&bH[(nb + tr)*PK1 + k0 + 8];
            bl[kt][0] = *(const uint32_t*)&bL[(nb + tr)*PK1 + k0];
            bl[kt][1] = *(const uint32_t*)&bL[(nb + tr)*PK1 + k0 + 8];
        }
        float4 acc = make_float4(0.f, 0.f, 0.f, 0.f);
        #pragma unroll
        for (int kt = 0; kt < 2; kt++) {
            mma_bf16(acc, ah[kt], bh[kt]);
            mma_bf16(acc, ah[kt], bl[kt]);
            mma_bf16(acc, al[kt], bh[kt]);
        }
        *(float2*)&op[(size_t)(rbase + tr    )*G1 + nb + tk] = make_float2(acc.x, acc.y);
        *(float2*)&op[(size_t)(rbase + tr + 8)*G1 + nb + tk] = make_float2(acc.z, acc.w);
    }
}

// ---------------------------------------------------------------------------
// zx2 = h1 @ W2 — bf16x3 mma, copy-only prologue, M=64/CTA, 2 CTAs/SM.
// grid (4096, 2). 8 warps: rows (wid&3)*16, N-half (wid>>2)*64.
// ---------------------------------------------------------------------------
#define PK2 136
#define ZX2_SMEM ((64*PK2*2 + 128*PK2*2) * 2)   // 104448 bytes

__global__ void __launch_bounds__(256, 2) zx2_gemm()
{
    extern __shared__ __nv_bfloat16 smb[];
    __nv_bfloat16* aH = smb;                 // [64][136]
    __nv_bfloat16* aL = aH + 64*PK2;
    __nv_bfloat16* bH = aL + 64*PK2;         // [128][136]
    __nv_bfloat16* bL = bH + 128*PK2;

    const int tid = threadIdx.x, wid = tid >> 5, lane = tid & 31;
    const size_t R0 = (size_t)blockIdx.x * 64;
    const int gb = blockIdx.y * 128;

    // B copy: 128 rows x 16 uint4 chunks
    for (int c = tid; c < 128*16; c += 256) {
        int gl = c >> 4, cc = c & 15;
        *(uint4*)&bH[gl*PK2 + cc*8] = ((const uint4*)(g_w2h + (size_t)(gb + gl)*H1C))[cc];
        *(uint4*)&bL[gl*PK2 + cc*8] = ((const uint4*)(g_w2l + (size_t)(gb + gl)*H1C))[cc];
    }
    // A copy: 64 rows x 16 uint4 chunks
    for (int c = tid; c < 64*16; c += 256) {
        int r = c >> 4, cc = c & 15;
        *(uint4*)&aH[r*PK2 + cc*8] = ((const uint4*)(g_h1h + (R0 + r)*H1C))[cc];
        *(uint4*)&aL[r*PK2 + cc*8] = ((const uint4*)(g_h1l + (R0 + r)*H1C))[cc];
    }
    __syncthreads();

    const int rw = (wid & 3) * 16;
    const int nbase = (wid >> 2) * 64;
    const int tr = lane >> 2;
    const int tk = (lane & 3) * 2;

    uint32_t ah[8][4], al[8][4];
    #pragma unroll
    for (int kt = 0; kt < 8; kt++) {
        int k0 = kt*16 + tk;
        ah[kt][0] = *(const uint32_t*)&aH[(rw + tr    )*PK2 + k0];
        ah[kt][1] = *(const uint32_t*)&aH[(rw + tr + 8)*PK2 + k0];
        ah[kt][2] = *(const uint32_t*)&aH[(rw + tr    )*PK2 + k0 + 8];
        ah[kt][3] = *(const uint32_t*)&aH[(rw + tr + 8)*PK2 + k0 + 8];
        al[kt][0] = *(const uint32_t*)&aL[(rw + tr    )*PK2 + k0];
        al[kt][1] = *(const uint32_t*)&aL[(rw + tr + 8)*PK2 + k0];
        al[kt][2] = *(const uint32_t*)&aL[(rw + tr    )*PK2 + k0 + 8];
        al[kt][3] = *(const uint32_t*)&aL[(rw + tr + 8)*PK2 + k0 + 8];
    }

    float* op = g_zx2 + R0 * G2 + gb;
    #pragma unroll 2
    for (int nt = 0; nt < 8; nt++) {
        int nb = nbase + nt * 8;
        float4 acc = make_float4(0.f, 0.f, 0.f, 0.f);
        #pragma unroll
        for (int kt = 0; kt < 8; kt++) {
            int k0 = kt*16 + tk;
            uint32_t bh[2], bl[2];
            bh[0] = *(const uint32_t*)&bH[(nb + tr)*PK2 + k0];
            bh[1] = *(const uint32_t*)&bH[(nb + tr)*PK2 + k0 + 8];
            bl[0] = *(const uint32_t*)&bL[(nb + tr)*PK2 + k0];
            bl[1] = *(const uint32_t*)&bL[(nb + tr)*PK2 + k0 + 8];
            mma_bf16(acc, ah[kt], bh);
            mma_bf16(acc, ah[kt], bl);
            mma_bf16(acc, al[kt], bh);
        }
        *(float2*)&op[(size_t)(rw + tr    )*G2 + nb + tk] = make_float2(acc.x, acc.y);
        *(float2*)&op[(size_t)(rw + tr + 8)*G2 + nb + tk] = make_float2(acc.z, acc.w);
    }
}

// ---------------------------------------------------------------------------
// LSTM1 recurrence (k=128) + BN1 — R8 exact, except h1 stored as bf16 hi/lo.
// ---------------------------------------------------------------------------
#define SMEM1_BYTES (48*G1*8 + 512*16 + 512*4)

__global__ void __launch_bounds__(512, 1) lstm1_kernel(
    const float* __restrict__ u1, const float* __restrict__ b1,
    const float* __restrict__ g1, const float* __restrict__ be1,
    const float* __restrict__ m1, const float* __restrict__ v1)
{
    extern __shared__ char smraw[];
    ull*    sUp = (ull*)smraw;               // [48][512]
    float4* sZ4 = (float4*)(sUp + 48*G1);    // [512]
    float*  sV  = (float*)(sZ4 + 512);       // [64 pairs][4][2]

    const int j  = threadIdx.x;
    const int r0 = blockIdx.x * RWS;
    const float* zx = g_zx1;

    ull rU[16];
    #pragma unroll
    for (int i = 0; i < 16; i++)
        rU[i] = pack2(u1[(2*i)*G1 + j], u1[(2*i+1)*G1 + j]);
    for (int i = 0; i < 48; i++)
        sUp[i*G1 + j] = pack2(u1[(32+2*i)*G1 + j], u1[(33+2*i)*G1 + j]);
    const float b1j = b1[j];

    const int rr = j >> 7, m = j & 127;
    const float bnsc = g1[m] / sqrtf(v1[m] + 1e-3f);
    const float bnsh = be1[m] - bnsc * m1[m];
    float creg = 0.f;

    sV[j] = 0.f;
    __syncthreads();

    float pz[4];
    #pragma unroll
    for (int i = 0; i < 4; i++)
        pz[i] = zx[((size_t)(r0 + i)*Tt + 0)*G1 + j];

    for (int t = 0; t < Tt; t++) {
        float nz[4] = {0.f, 0.f, 0.f, 0.f};
        const bool pf = (t + 1 < Tt);
        if (pf) {
            #pragma unroll
            for (int i = 0; i < 4; i++)
                nz[i] = zx[((size_t)(r0 + i)*Tt + t + 1)*G1 + j];
        }
        ull a0 = pack2(pz[0], b1j);
        ull a1 = pack2(pz[1], b1j);
        ull a2 = pack2(pz[2], b1j);
        ull a3 = pack2(pz[3], b1j);

        const ulonglong2* hv2 = (const ulonglong2*)sV;
        #pragma unroll
        for (int i = 0; i < 16; i++) {
            ulonglong2 hA = hv2[i*2];
            ulonglong2 hB = hv2[i*2 + 1];
            ffma2(a0, rU[i], hA.x);
            ffma2(a1, rU[i], hA.y);
            ffma2(a2, rU[i], hB.x);
            ffma2(a3, rU[i], hB.y);
        }
        #pragma unroll 8
        for (int i = 0; i < 48; i++) {
            ull u2 = sUp[i*G1 + j];
            ulonglong2 hA = hv2[(16+i)*2];
            ulonglong2 hB = hv2[(16+i)*2 + 1];
            ffma2(a0, u2, hA.x);
            ffma2(a1, u2, hA.y);
            ffma2(a2, u2, hB.x);
            ffma2(a3, u2, hB.y);
        }
        float2 f0 = unpk2(a0), f1 = unpk2(a1), f2 = unpk2(a2), f3 = unpk2(a3);
        sZ4[j] = make_float4(f0.x + f0.y, f1.x + f1.y, f2.x + f2.y, f3.x + f3.y);
        __syncthreads();

        const float* zf = (const float*)sZ4;
        float zi = zf[(m      )*4 + rr];
        float zfv= zf[(m + 128)*4 + rr];
        float zg = zf[(m + 256)*4 + rr];
        float zo = zf[(m + 384)*4 + rr];
        float ig = sigf(zi), fg = sigf(zfv), og = sigf(zo);
        float gg = fmaxf(zg, 0.f);
        creg = fmaf(fg, creg, ig * gg);
        float h = og * fmaxf(creg, 0.f);
        sV[(m>>1)*8 + rr*2 + (m&1)] = h;
        float bnh = fmaf(h, bnsc, bnsh);
        size_t oidx = ((size_t)(r0 + rr)*Tt + t)*H1C + m;
        __nv_bfloat16 hh, hl;
        split_bf16(bnh, hh, hl);
        g_h1h[oidx] = hh;
        g_h1l[oidx] = hl;
        #pragma unroll
        for (int i = 0; i < 4; i++) pz[i] = nz[i];
        __syncthreads();
    }
}

// ---------------------------------------------------------------------------
// LSTM2 recurrence (k=64) + BN2 — R8 exact.
// ---------------------------------------------------------------------------
#define SMEM2_BYTES (512*16 + 256*4)

__global__ void __launch_bounds__(512, 1) lstm2_kernel(
    const float* __restrict__ u2, const float* __restrict__ b2,
    const float* __restrict__ g2, const float* __restrict__ be2,
    const float* __restrict__ m2, const float* __restrict__ v2)
{
    extern __shared__ char smraw[];
    float4* sZp = (float4*)smraw;            // [2][256]
    float*  sV  = (float*)(sZp + 512);       // [32 pairs][4][2]

    const int j    = threadIdx.x;
    const int jc   = j & 255;
    const int half = j >> 8;
    const int r0   = blockIdx.x * RWS;
    const float* zx = g_zx2;

    ull rW[16];
    #pragma unroll
    for (int p = 0; p < 16; p++)
        rW[p] = pack2(u2[(32*half + 2*p)*G2 + jc], u2[(32*half + 2*p + 1)*G2 + jc]);
    const float bj = b2[jc];

    const int rr = jc >> 6, m = j & 63;
    const float bnsc = g2[m] / sqrtf(v2[m] + 1e-3f);
    const float bnsh = be2[m] - bnsc * m2[m];
    float creg = 0.f;

    if (j < 256) sV[j] = 0.f;
    __syncthreads();

    float pz[4] = {0.f, 0.f, 0.f, 0.f};
    if (half == 0) {
        #pragma unroll
        for (int i = 0; i < 4; i++)
            pz[i] = zx[((size_t)(r0 + i)*Tt + 0)*G2 + jc];
    }

    for (int t = 0; t < Tt; t++) {
        float nz[4] = {0.f, 0.f, 0.f, 0.f};
        const bool pf = (t + 1 < Tt);
        if (pf && half == 0) {
            #pragma unroll
            for (int i = 0; i < 4; i++)
                nz[i] = zx[((size_t)(r0 + i)*Tt + t + 1)*G2 + jc];
        }
        ull a0, a1, a2, a3;
        if (half == 0) {
            a0 = pack2(pz[0], bj); a1 = pack2(pz[1], bj);
            a2 = pack2(pz[2], bj); a3 = pack2(pz[3], bj);
        } else {
            a0 = pack2(0.f, 0.f); a1 = a0; a2 = a0; a3 = a0;
        }
        const ulonglong2* hv2 = (const ulonglong2*)sV;
        const int gb = 16 * half;
        #pragma unroll
        for (int p = 0; p < 16; p++) {
            ulonglong2 hA = hv2[(gb + p)*2];
            ulonglong2 hB = hv2[(gb + p)*2 + 1];
            ffma2(a0, rW[p], hA.x);
            ffma2(a1, rW[p], hA.y);
            ffma2(a2, rW[p], hB.x);
            ffma2(a3, rW[p], hB.y);
        }
        float2 f0 = unpk2(a0), f1 = unpk2(a1), f2 = unpk2(a2), f3 = unpk2(a3);
        sZp[half*G2 + jc] = make_float4(f0.x + f0.y, f1.x + f1.y, f2.x + f2.y, f3.x + f3.y);
        __syncthreads();

        if (j < 256) {
            const float* zf = (const float*)sZp;
            float zi = zf[(m      )*4 + rr] + zf[(256 + m      )*4 + rr];
            float zfv= zf[(m +  64)*4 + rr] + zf[(256 + m +  64)*4 + rr];
            float zg = zf[(m + 128)*4 + rr] + zf[(256 + m + 128)*4 + rr];
            float zo = zf[(m + 192)*4 + rr] + zf[(256 + m + 192)*4 + rr];
            float ig = sigf(zi), fg = sigf(zfv), og = sigf(zo);
            float gg = fmaxf(zg, 0.f);
            creg = fmaf(fg, creg, ig * gg);
            float h = og * fmaxf(creg, 0.f);
            sV[(m>>1)*8 + rr*2 + (m&1)] = h;
            if (t == Tt - 1)
                g_h2[(r0 + rr)*H2C + m] = fmaf(h, bnsc, bnsh);
        }
        #pragma unroll
        for (int i = 0; i < 4; i++) pz[i] = nz[i];
        __syncthreads();
    }
}

// ---------------------------------------------------------------------------
// head: logits + exp. 125 CTAs x 256 vocab columns.
// ---------------------------------------------------------------------------
#define H2T_STRIDE 514
#define SMEM3_BYTES (H2C * H2T_STRIDE * 4)

__global__ void __launch_bounds__(256, 1) head_kernel(
    const float* __restrict__ wd, const float* __restrict__ bd,
    float* __restrict__ out)
{
    extern __shared__ float sH2t[];
    const int j = threadIdx.x;
    const int v = blockIdx.x * 256 + j;

    for (int i = j; i < Bsz*H2C; i += 256) {
        int r = i >> 6, k = i & 63;
        sH2t[k*H2T_STRIDE + r] = g_h2[i];
    }
    ull rwd2[H2C];
    #pragma unroll
    for (int k = 0; k < H2C; k++) {
        float w = wd[(size_t)k*VV + v];
        rwd2[k] = pack2(w, w);
    }
    const float bdv = bd[v];
    const ull bb = pack2(bdv, bdv);
    __syncthreads();

    for (int r = 0; r < Bsz; r += 4) {
        ull a01 = bb, a23 = bb;
        #pragma unroll 16
        for (int k = 0; k < H2C; k++) {
            const float* hp = sH2t + k*H2T_STRIDE + r;
            ull h01 = *(const ull*)(hp);
            ull h23 = *(const ull*)(hp + 2);
            ffma2(a01, rwd2[k], h01);
            ffma2(a23, rwd2[k], h23);
        }
        float2 f01 = unpk2(a01), f23 = unpk2(a23);
        out[(size_t)(r + 0)*VV + v] = __expf(f01.x);
        out[(size_t)(r + 1)*VV + v] = __expf(f01.y);
        out[(size_t)(r + 2)*VV + v] = __expf(f23.x);
        out[(size_t)(r + 3)*VV + v] = __expf(f23.y);
    }
}

// ---------------------------------------------------------------------------
// per-row softmax normalize.
// ---------------------------------------------------------------------------
__global__ void __launch_bounds__(256, 1) softmax_norm_kernel(float* __restrict__ out)
{
    __shared__ float warp_s[8];
    __shared__ float inv_s;
    const int r = blockIdx.x;
    float4* p = (float4*)(out + (size_t)r * VV);

    float s = 0.f;
    for (int i = threadIdx.x; i < VV/4; i += 256) {
        float4 v = p[i];
        s += (v.x + v.y) + (v.z + v.w);
    }
    #pragma unroll
    for (int o = 16; o > 0; o >>= 1) s += __shfl_down_sync(0xffffffffu, s, o);
    if ((threadIdx.x & 31) == 0) warp_s[threadIdx.x >> 5] = s;
    __syncthreads();
    if (threadIdx.x == 0) {
        float tt = 0.f;
        #pragma unroll
        for (int i = 0; i < 8; i++) tt += warp_s[i];
        inv_s = 1.0f / tt;
    }
    __syncthreads();
    const float inv = inv_s;
    for (int i = threadIdx.x; i < VV/4; i += 256) {
        float4 v = p[i];
        v.x *= inv; v.y *= inv; v.z *= inv; v.w *= inv;
        p[i] = v;
    }
}

// ---------------------------------------------------------------------------
extern "C" void kernel_launch(void* const* d_in, const int* in_sizes, int n_in,
                              void* d_out, int out_size)
{
    const int*   ids = (const int*)  d_in[0];
    const float* emb = (const float*)d_in[1];
    const float* w1  = (const float*)d_in[2];
    const float* u1  = (const float*)d_in[3];
    const float* b1  = (const float*)d_in[4];
    const float* g1  = (const float*)d_in[5];
    const float* be1 = (const float*)d_in[6];
    const float* m1  = (const float*)d_in[7];
    const float* v1  = (const float*)d_in[8];
    const float* w2  = (const float*)d_in[9];
    const float* u2  = (const float*)d_in[10];
    const float* b2  = (const float*)d_in[11];
    const float* g2  = (const float*)d_in[12];
    const float* be2 = (const float*)d_in[13];
    const float* m2  = (const float*)d_in[14];
    const float* v2  = (const float*)d_in[15];
    const float* wd  = (const float*)d_in[16];
    const float* bd  = (const float*)d_in[17];
    float* out = (float*)d_out;

    cudaFuncSetAttribute(zx1_gemm,     cudaFuncAttributeMaxDynamicSharedMemorySize, ZX1_SMEM);
    cudaFuncSetAttribute(zx2_gemm,     cudaFuncAttributeMaxDynamicSharedMemorySize, ZX2_SMEM);
    cudaFuncSetAttribute(lstm1_kernel, cudaFuncAttributeMaxDynamicSharedMemorySize, SMEM1_BYTES);
    cudaFuncSetAttribute(lstm2_kernel, cudaFuncAttributeMaxDynamicSharedMemorySize, SMEM2_BYTES);
    cudaFuncSetAttribute(head_kernel,  cudaFuncAttributeMaxDynamicSharedMemorySize, SMEM3_BYTES);

    split_w_kernel<<<192, 256>>>(w1, w2);                                  // 1
    zx1_gemm<<<NR/128, 256, ZX1_SMEM>>>(ids, emb);                         // 2
    lstm1_kernel<<<Bsz/RWS, 512, SMEM1_BYTES>>>(u1, b1, g1, be1, m1, v1);  // 3
    zx2_gemm<<<dim3(NR/64, 2), 256, ZX2_SMEM>>>();                         // 4 <- captured
    lstm2_kernel<<<Bsz/RWS, 512, SMEM2_BYTES>>>(u2, b2, g2, be2, m2, v2);  // 5
    head_kernel<<<VV/256, 256, SMEM3_BYTES>>>(wd, bd, out);                // 6
    softmax_norm_kernel<<<Bsz, 256>>>(out);                                // 7
}